// round 1
// baseline (speedup 1.0000x reference)
#include <cuda_runtime.h>
#include <math.h>

// Problem constants
#define BATCH 2
#define SEQ   2048
#define DIM   1024
#define HEADS 16
#define DKH   64
#define MTOT  (BATCH * SEQ)   // 4096

// Scratch buffers (device globals — no allocation allowed)
__device__ float g_qp[MTOT * DIM];
__device__ float g_kp[MTOT * DIM];
__device__ float g_vp[MTOT * DIM];
__device__ float g_ao[MTOT * DIM];

// ---------------------------------------------------------------------------
// SGEMM: C[M,N] = A[M,K] @ W[N,K]^T   (both row-major, K contiguous — "NT")
// BM=128, BN=128, BK=16, 256 threads, 8x8 per thread.
// ---------------------------------------------------------------------------
__global__ __launch_bounds__(256) void sgemm_nt(const float* __restrict__ A,
                                                const float* __restrict__ W,
                                                float* __restrict__ C,
                                                int M, int N, int K) {
    __shared__ float As[16][128];
    __shared__ float Bs[16][128];

    const int tid = threadIdx.x;
    const int bm = blockIdx.y * 128;
    const int bn = blockIdx.x * 128;
    const int tx = tid & 15;    // 0..15
    const int ty = tid >> 4;    // 0..15

    float acc[8][8];
#pragma unroll
    for (int i = 0; i < 8; i++)
#pragma unroll
        for (int j = 0; j < 8; j++) acc[i][j] = 0.f;

    for (int k0 = 0; k0 < K; k0 += 16) {
        // Load 128x16 tiles of A and W, transposed into smem.
#pragma unroll
        for (int it = 0; it < 2; it++) {
            int id = tid + it * 256;      // 0..511
            int row = id >> 2;            // 0..127
            int seg = id & 3;             // 0..3  (float4 segment within the 16 k's)
            float4 va = *(const float4*)(A + (size_t)(bm + row) * K + k0 + seg * 4);
            As[seg * 4 + 0][row] = va.x;
            As[seg * 4 + 1][row] = va.y;
            As[seg * 4 + 2][row] = va.z;
            As[seg * 4 + 3][row] = va.w;
            float4 vb = *(const float4*)(W + (size_t)(bn + row) * K + k0 + seg * 4);
            Bs[seg * 4 + 0][row] = vb.x;
            Bs[seg * 4 + 1][row] = vb.y;
            Bs[seg * 4 + 2][row] = vb.z;
            Bs[seg * 4 + 3][row] = vb.w;
        }
        __syncthreads();

#pragma unroll
        for (int k = 0; k < 16; k++) {
            float a[8], b[8];
            const float4* ar = (const float4*)&As[k][ty * 8];
            const float4* br = (const float4*)&Bs[k][tx * 8];
            float4 a0 = ar[0], a1 = ar[1];
            float4 b0 = br[0], b1 = br[1];
            a[0] = a0.x; a[1] = a0.y; a[2] = a0.z; a[3] = a0.w;
            a[4] = a1.x; a[5] = a1.y; a[6] = a1.z; a[7] = a1.w;
            b[0] = b0.x; b[1] = b0.y; b[2] = b0.z; b[3] = b0.w;
            b[4] = b1.x; b[5] = b1.y; b[6] = b1.z; b[7] = b1.w;
#pragma unroll
            for (int i = 0; i < 8; i++)
#pragma unroll
                for (int j = 0; j < 8; j++) acc[i][j] += a[i] * b[j];
        }
        __syncthreads();
    }

#pragma unroll
    for (int i = 0; i < 8; i++) {
        float* cp = C + (size_t)(bm + ty * 8 + i) * N + bn + tx * 8;
        float4 v0 = make_float4(acc[i][0], acc[i][1], acc[i][2], acc[i][3]);
        float4 v1 = make_float4(acc[i][4], acc[i][5], acc[i][6], acc[i][7]);
        *(float4*)(cp + 0) = v0;
        *(float4*)(cp + 4) = v1;
    }
}

// ---------------------------------------------------------------------------
// Flash-style attention.
// Grid: (SEQ/64, HEADS, BATCH). Block: 256 threads.
// Thread tid: qr = tid/4 (q row within 64-row tile), c = tid%4
//   - owns output dk columns [c*16, c*16+16)
//   - in score phase computes keys kk = jj*4 + c, jj = 0..7 (32-key k-tile)
// Online softmax state (m, l) replicated across the 4-thread quad via shuffles.
// Masked positions get score 1e-9 BEFORE softmax (faithful to reference).
// ---------------------------------------------------------------------------
__global__ __launch_bounds__(256) void attn_kernel(const float* __restrict__ Qp,
                                                   const float* __restrict__ Kp,
                                                   const float* __restrict__ Vp,
                                                   const int* __restrict__ mask,
                                                   float* __restrict__ O) {
    __shared__ float Qs[64][68];   // padded: float4-aligned rows, conflict-avoiding
    __shared__ float Ks[32][68];
    __shared__ float Vs[32][68];
    __shared__ float Ps[64][33];

    const int tid = threadIdx.x;
    const int q0 = blockIdx.x * 64;
    const int h  = blockIdx.y;
    const int b  = blockIdx.z;
    const int qr = tid >> 2;
    const int c  = tid & 3;

    const size_t base = (size_t)b * SEQ * DIM + (size_t)h * DKH;

    // Load Q tile [64][64], pre-scaled by 1/sqrt(DK) = 0.125
#pragma unroll
    for (int it = 0; it < 4; it++) {
        int id = tid + it * 256;   // 0..1023
        int r  = id >> 4;          // 0..63
        int d4 = id & 15;          // 0..15
        float4 v = *(const float4*)(Qp + base + (size_t)(q0 + r) * DIM + d4 * 4);
        v.x *= 0.125f; v.y *= 0.125f; v.z *= 0.125f; v.w *= 0.125f;
        *(float4*)&Qs[r][d4 * 4] = v;
    }

    float acc[16];
#pragma unroll
    for (int i = 0; i < 16; i++) acc[i] = 0.f;
    float mrow = -INFINITY;
    float lrow = 0.f;

    const int* mbase = mask + (size_t)b * SEQ * SEQ + (size_t)(q0 + qr) * SEQ;

    for (int k0 = 0; k0 < SEQ; k0 += 32) {
        // Load K and V tiles [32][64]
#pragma unroll
        for (int it = 0; it < 2; it++) {
            int id = tid + it * 256;   // 0..511
            int r  = id >> 4;          // 0..31
            int d4 = id & 15;
            *(float4*)&Ks[r][d4 * 4] =
                *(const float4*)(Kp + base + (size_t)(k0 + r) * DIM + d4 * 4);
            *(float4*)&Vs[r][d4 * 4] =
                *(const float4*)(Vp + base + (size_t)(k0 + r) * DIM + d4 * 4);
        }
        __syncthreads();

        // Scores for this thread's 8 keys
        float sv[8];
        float tmax = -INFINITY;
        const float4* q4 = (const float4*)&Qs[qr][0];
#pragma unroll
        for (int jj = 0; jj < 8; jj++) {
            int kk = jj * 4 + c;
            const float4* k4 = (const float4*)&Ks[kk][0];
            float s = 0.f;
#pragma unroll
            for (int d = 0; d < 16; d++) {
                float4 a = q4[d];
                float4 kb = k4[d];
                s += a.x * kb.x + a.y * kb.y + a.z * kb.z + a.w * kb.w;
            }
            int mv = mbase[k0 + kk];
            s = (mv == 0) ? 1e-9f : s;
            sv[jj] = s;
            tmax = fmaxf(tmax, s);
        }
        // Row max across the 4-thread quad
        tmax = fmaxf(tmax, __shfl_xor_sync(0xffffffffu, tmax, 1));
        tmax = fmaxf(tmax, __shfl_xor_sync(0xffffffffu, tmax, 2));
        float mnew  = fmaxf(mrow, tmax);
        float scale = __expf(mrow - mnew);   // first tile: exp(-inf)=0

        float psum = 0.f;
#pragma unroll
        for (int jj = 0; jj < 8; jj++) {
            float p = __expf(sv[jj] - mnew);
            Ps[qr][jj * 4 + c] = p;
            psum += p;
        }
        psum += __shfl_xor_sync(0xffffffffu, psum, 1);
        psum += __shfl_xor_sync(0xffffffffu, psum, 2);
        lrow = lrow * scale + psum;
        mrow = mnew;

#pragma unroll
        for (int i = 0; i < 16; i++) acc[i] *= scale;

        __syncwarp();   // Ps row produced by the quad (same warp)

        // acc += P_row @ V_tile  (this thread's 16 dk columns)
#pragma unroll
        for (int kk = 0; kk < 32; kk++) {
            float p = Ps[qr][kk];
            const float4* v4 = (const float4*)&Vs[kk][c * 16];
#pragma unroll
            for (int i4 = 0; i4 < 4; i4++) {
                float4 vv = v4[i4];
                acc[i4 * 4 + 0] += p * vv.x;
                acc[i4 * 4 + 1] += p * vv.y;
                acc[i4 * 4 + 2] += p * vv.z;
                acc[i4 * 4 + 3] += p * vv.w;
            }
        }
        __syncthreads();   // protect Ks/Vs/Ps before next tile's overwrite
    }

    float inv = 1.f / lrow;
    float* op = O + base + (size_t)(q0 + qr) * DIM + c * 16;
#pragma unroll
    for (int i4 = 0; i4 < 4; i4++) {
        float4 vv = make_float4(acc[i4 * 4 + 0] * inv, acc[i4 * 4 + 1] * inv,
                                acc[i4 * 4 + 2] * inv, acc[i4 * 4 + 3] * inv);
        *(float4*)(op + i4 * 4) = vv;
    }
}

// ---------------------------------------------------------------------------
// Launch
// ---------------------------------------------------------------------------
extern "C" void kernel_launch(void* const* d_in, const int* in_sizes, int n_in,
                              void* d_out, int out_size) {
    const float* Q    = (const float*)d_in[0];
    const float* K    = (const float*)d_in[1];
    const float* V    = (const float*)d_in[2];
    const int*   mask = (const int*)d_in[3];
    const float* Wq   = (const float*)d_in[4];
    const float* Wk   = (const float*)d_in[5];
    const float* Wv   = (const float*)d_in[6];
    const float* Wo   = (const float*)d_in[7];
    float* out = (float*)d_out;

    float *qp, *kp, *vp, *ao;
    cudaGetSymbolAddress((void**)&qp, g_qp);
    cudaGetSymbolAddress((void**)&kp, g_kp);
    cudaGetSymbolAddress((void**)&vp, g_vp);
    cudaGetSymbolAddress((void**)&ao, g_ao);

    dim3 gsz(DIM / 128, MTOT / 128);   // (8, 32)
    sgemm_nt<<<gsz, 256>>>(Q, Wq, qp, MTOT, DIM, DIM);
    sgemm_nt<<<gsz, 256>>>(K, Wk, kp, MTOT, DIM, DIM);
    sgemm_nt<<<gsz, 256>>>(V, Wv, vp, MTOT, DIM, DIM);

    dim3 agrid(SEQ / 64, HEADS, BATCH);   // (32, 16, 2)
    attn_kernel<<<agrid, 256>>>(qp, kp, vp, mask, ao);

    sgemm_nt<<<gsz, 256>>>(ao, Wo, out, MTOT, DIM, DIM);
}

// round 2
// speedup vs baseline: 1.9461x; 1.9461x over previous
#include <cuda_runtime.h>
#include <math.h>

// Problem constants
#define BATCH 2
#define SEQ   2048
#define DIM   1024
#define HEADS 16
#define DKH   64
#define MTOT  (BATCH * SEQ)   // 4096

// Scratch buffers (device globals — no allocation allowed)
__device__ float g_qp[MTOT * DIM];
__device__ float g_kp[MTOT * DIM];
__device__ float g_vp[MTOT * DIM];
__device__ float g_ao[MTOT * DIM];

// ---------------------------------------------------------------------------
// SGEMM: C[M,N] = A[M,K] @ W[N,K]^T   (both row-major, K contiguous — "NT")
// BM=128, BN=128, BK=16, 256 threads, 8x8 per thread.  (at fp32 FMA roofline)
// ---------------------------------------------------------------------------
__global__ __launch_bounds__(256) void sgemm_nt(const float* __restrict__ A,
                                                const float* __restrict__ W,
                                                float* __restrict__ C,
                                                int M, int N, int K) {
    __shared__ float As[16][128];
    __shared__ float Bs[16][128];

    const int tid = threadIdx.x;
    const int bm = blockIdx.y * 128;
    const int bn = blockIdx.x * 128;
    const int tx = tid & 15;    // 0..15
    const int ty = tid >> 4;    // 0..15

    float acc[8][8];
#pragma unroll
    for (int i = 0; i < 8; i++)
#pragma unroll
        for (int j = 0; j < 8; j++) acc[i][j] = 0.f;

    for (int k0 = 0; k0 < K; k0 += 16) {
#pragma unroll
        for (int it = 0; it < 2; it++) {
            int id = tid + it * 256;      // 0..511
            int row = id >> 2;            // 0..127
            int seg = id & 3;             // 0..3
            float4 va = *(const float4*)(A + (size_t)(bm + row) * K + k0 + seg * 4);
            As[seg * 4 + 0][row] = va.x;
            As[seg * 4 + 1][row] = va.y;
            As[seg * 4 + 2][row] = va.z;
            As[seg * 4 + 3][row] = va.w;
            float4 vb = *(const float4*)(W + (size_t)(bn + row) * K + k0 + seg * 4);
            Bs[seg * 4 + 0][row] = vb.x;
            Bs[seg * 4 + 1][row] = vb.y;
            Bs[seg * 4 + 2][row] = vb.z;
            Bs[seg * 4 + 3][row] = vb.w;
        }
        __syncthreads();

#pragma unroll
        for (int k = 0; k < 16; k++) {
            float a[8], b[8];
            const float4* ar = (const float4*)&As[k][ty * 8];
            const float4* br = (const float4*)&Bs[k][tx * 8];
            float4 a0 = ar[0], a1 = ar[1];
            float4 b0 = br[0], b1 = br[1];
            a[0] = a0.x; a[1] = a0.y; a[2] = a0.z; a[3] = a0.w;
            a[4] = a1.x; a[5] = a1.y; a[6] = a1.z; a[7] = a1.w;
            b[0] = b0.x; b[1] = b0.y; b[2] = b0.z; b[3] = b0.w;
            b[4] = b1.x; b[5] = b1.y; b[6] = b1.z; b[7] = b1.w;
#pragma unroll
            for (int i = 0; i < 8; i++)
#pragma unroll
                for (int j = 0; j < 8; j++) acc[i][j] += a[i] * b[j];
        }
        __syncthreads();
    }

#pragma unroll
    for (int i = 0; i < 8; i++) {
        float* cp = C + (size_t)(bm + ty * 8 + i) * N + bn + tx * 8;
        *(float4*)(cp + 0) = make_float4(acc[i][0], acc[i][1], acc[i][2], acc[i][3]);
        *(float4*)(cp + 4) = make_float4(acc[i][4], acc[i][5], acc[i][6], acc[i][7]);
    }
}

// ---------------------------------------------------------------------------
// Flash attention, register-tiled.
// Grid: (SEQ/64, HEADS, BATCH). Block: 256 threads as 16x16:
//   ty = tid>>4 owns q-rows  [ty*4, ty*4+4)
//   tx = tid&15 owns keys    [tx*4, tx*4+4)  in score phase
//                 and dk-cols[tx*4, tx*4+4)  in AV phase
// Q^T and K^T in smem feed 4x4 outer-product tiles (2 LDS.128 per 16 FMA).
// P reuses K's smem region (score reads K, then after a sync P overwrites it).
// Smem = 3 * 16KB = 48KB static.
// ---------------------------------------------------------------------------
__global__ __launch_bounds__(256) void attn_kernel(const float* __restrict__ Qp,
                                                   const float* __restrict__ Kp,
                                                   const float* __restrict__ Vp,
                                                   const int* __restrict__ mask,
                                                   float* __restrict__ O) {
    __shared__ float Qt[64 * 64];   // Q^T: Qt[d*64 + row], pre-scaled by 1/8
    __shared__ float KP[64 * 64];   // K^T: KP[d*64 + key]  /  P: KP[row*64 + key]
    __shared__ float Vs[64 * 64];   // V:   Vs[key*64 + dk]

    const int tid = threadIdx.x;
    const int q0 = blockIdx.x * 64;
    const int h  = blockIdx.y;
    const int b  = blockIdx.z;
    const int tx = tid & 15;
    const int ty = tid >> 4;

    const size_t base = (size_t)b * SEQ * DIM + (size_t)h * DKH;

    // Load Q tile [64 rows][64 d] transposed, scaled by 1/sqrt(64)=0.125.
#pragma unroll
    for (int it = 0; it < 4; it++) {
        int id = tid + it * 256;   // 0..1023
        int r  = id >> 4;          // row 0..63
        int d4 = id & 15;          // float4 chunk 0..15
        float4 v = *(const float4*)(Qp + base + (size_t)(q0 + r) * DIM + d4 * 4);
        Qt[(d4 * 4 + 0) * 64 + r] = v.x * 0.125f;
        Qt[(d4 * 4 + 1) * 64 + r] = v.y * 0.125f;
        Qt[(d4 * 4 + 2) * 64 + r] = v.z * 0.125f;
        Qt[(d4 * 4 + 3) * 64 + r] = v.w * 0.125f;
    }

    float acc[4][4];
#pragma unroll
    for (int i = 0; i < 4; i++)
#pragma unroll
        for (int j = 0; j < 4; j++) acc[i][j] = 0.f;
    float m[4], l[4];
#pragma unroll
    for (int i = 0; i < 4; i++) { m[i] = -INFINITY; l[i] = 0.f; }

    const int* mbase = mask + (size_t)b * SEQ * SEQ;

    for (int k0 = 0; k0 < SEQ; k0 += 64) {
        __syncthreads();   // prior AV phase done with KP/Vs

        // Load K tile transposed into KP; V tile natural into Vs.
#pragma unroll
        for (int it = 0; it < 4; it++) {
            int id = tid + it * 256;
            int r  = id >> 4;      // key 0..63
            int d4 = id & 15;
            float4 kv = *(const float4*)(Kp + base + (size_t)(k0 + r) * DIM + d4 * 4);
            KP[(d4 * 4 + 0) * 64 + r] = kv.x;
            KP[(d4 * 4 + 1) * 64 + r] = kv.y;
            KP[(d4 * 4 + 2) * 64 + r] = kv.z;
            KP[(d4 * 4 + 3) * 64 + r] = kv.w;
            *(float4*)&Vs[r * 64 + d4 * 4] =
                *(const float4*)(Vp + base + (size_t)(k0 + r) * DIM + d4 * 4);
        }

        // Prefetch mask: 4 rows x 4 keys
        int4 mv[4];
#pragma unroll
        for (int i = 0; i < 4; i++)
            mv[i] = *(const int4*)(mbase + (size_t)(q0 + ty * 4 + i) * SEQ + k0 + tx * 4);

        __syncthreads();

        // Score: S[4 rows][4 keys] = (Q/8) @ K^T
        float s[4][4];
#pragma unroll
        for (int i = 0; i < 4; i++)
#pragma unroll
            for (int j = 0; j < 4; j++) s[i][j] = 0.f;

#pragma unroll 8
        for (int d = 0; d < 64; d++) {
            float4 qv = *(const float4*)&Qt[d * 64 + ty * 4];
            float4 kv = *(const float4*)&KP[d * 64 + tx * 4];
            float qa[4] = {qv.x, qv.y, qv.z, qv.w};
            float ka[4] = {kv.x, kv.y, kv.z, kv.w};
#pragma unroll
            for (int i = 0; i < 4; i++)
#pragma unroll
                for (int j = 0; j < 4; j++) acc[0][0] == acc[0][0] ? (s[i][j] += qa[i] * ka[j]) : 0.f;
        }

        // Mask (value 1e-9 BEFORE softmax, faithful to reference)
        {
            int mm[4][4];
#pragma unroll
            for (int i = 0; i < 4; i++) {
                mm[i][0] = mv[i].x; mm[i][1] = mv[i].y; mm[i][2] = mv[i].z; mm[i][3] = mv[i].w;
            }
#pragma unroll
            for (int i = 0; i < 4; i++)
#pragma unroll
                for (int j = 0; j < 4; j++)
                    s[i][j] = (mm[i][j] == 0) ? 1e-9f : s[i][j];
        }

        // Row stats: max/sum across the 16 tx-lanes (same 16-lane half-warp)
        float mn[4], sc[4], ps[4];
#pragma unroll
        for (int i = 0; i < 4; i++) {
            float tm = fmaxf(fmaxf(s[i][0], s[i][1]), fmaxf(s[i][2], s[i][3]));
#pragma unroll
            for (int w = 1; w < 16; w <<= 1)
                tm = fmaxf(tm, __shfl_xor_sync(0xffffffffu, tm, w));
            mn[i] = fmaxf(m[i], tm);
            sc[i] = __expf(m[i] - mn[i]);
            float p0 = __expf(s[i][0] - mn[i]);
            float p1 = __expf(s[i][1] - mn[i]);
            float p2 = __expf(s[i][2] - mn[i]);
            float p3 = __expf(s[i][3] - mn[i]);
            s[i][0] = p0; s[i][1] = p1; s[i][2] = p2; s[i][3] = p3;
            float sum = p0 + p1 + p2 + p3;
#pragma unroll
            for (int w = 1; w < 16; w <<= 1)
                sum += __shfl_xor_sync(0xffffffffu, sum, w);
            ps[i] = sum;
        }

        __syncthreads();   // everyone done reading KP (K^T) before P overwrite

        // Store P into KP region: P[row][key]
#pragma unroll
        for (int i = 0; i < 4; i++)
            *(float4*)&KP[(ty * 4 + i) * 64 + tx * 4] =
                make_float4(s[i][0], s[i][1], s[i][2], s[i][3]);

        // Update state + rescale accumulators
#pragma unroll
        for (int i = 0; i < 4; i++) {
            l[i] = l[i] * sc[i] + ps[i];
            m[i] = mn[i];
#pragma unroll
            for (int j = 0; j < 4; j++) acc[i][j] *= sc[i];
        }

        __syncthreads();   // P visible to all

        // AV: acc[4 rows][4 dk] += P[rows][keys] @ V[keys][dk]
#pragma unroll 4
        for (int kc = 0; kc < 16; kc++) {
            float4 pv[4];
#pragma unroll
            for (int i = 0; i < 4; i++)
                pv[i] = *(const float4*)&KP[(ty * 4 + i) * 64 + kc * 4];
#pragma unroll
            for (int jj = 0; jj < 4; jj++) {
                float4 vv = *(const float4*)&Vs[(kc * 4 + jj) * 64 + tx * 4];
                float pj[4] = { ((const float*)&pv[0])[jj], ((const float*)&pv[1])[jj],
                                ((const float*)&pv[2])[jj], ((const float*)&pv[3])[jj] };
#pragma unroll
                for (int i = 0; i < 4; i++) {
                    acc[i][0] += pj[i] * vv.x;
                    acc[i][1] += pj[i] * vv.y;
                    acc[i][2] += pj[i] * vv.z;
                    acc[i][3] += pj[i] * vv.w;
                }
            }
        }
    }

    // Epilogue
#pragma unroll
    for (int i = 0; i < 4; i++) {
        float inv = 1.f / l[i];
        float* op = O + base + (size_t)(q0 + ty * 4 + i) * DIM + tx * 4;
        *(float4*)op = make_float4(acc[i][0] * inv, acc[i][1] * inv,
                                   acc[i][2] * inv, acc[i][3] * inv);
    }
}

// ---------------------------------------------------------------------------
// Launch
// ---------------------------------------------------------------------------
extern "C" void kernel_launch(void* const* d_in, const int* in_sizes, int n_in,
                              void* d_out, int out_size) {
    const float* Q    = (const float*)d_in[0];
    const float* K    = (const float*)d_in[1];
    const float* V    = (const float*)d_in[2];
    const int*   mask = (const int*)d_in[3];
    const float* Wq   = (const float*)d_in[4];
    const float* Wk   = (const float*)d_in[5];
    const float* Wv   = (const float*)d_in[6];
    const float* Wo   = (const float*)d_in[7];
    float* out = (float*)d_out;

    float *qp, *kp, *vp, *ao;
    cudaGetSymbolAddress((void**)&qp, g_qp);
    cudaGetSymbolAddress((void**)&kp, g_kp);
    cudaGetSymbolAddress((void**)&vp, g_vp);
    cudaGetSymbolAddress((void**)&ao, g_ao);

    dim3 gsz(DIM / 128, MTOT / 128);   // (8, 32)
    sgemm_nt<<<gsz, 256>>>(Q, Wq, qp, MTOT, DIM, DIM);
    sgemm_nt<<<gsz, 256>>>(K, Wk, kp, MTOT, DIM, DIM);
    sgemm_nt<<<gsz, 256>>>(V, Wv, vp, MTOT, DIM, DIM);

    dim3 agrid(SEQ / 64, HEADS, BATCH);   // (32, 16, 2)
    attn_kernel<<<agrid, 256>>>(qp, kp, vp, mask, ao);

    sgemm_nt<<<gsz, 256>>>(ao, Wo, out, MTOT, DIM, DIM);
}

// round 3
// speedup vs baseline: 3.0753x; 1.5802x over previous
#include <cuda_runtime.h>
#include <math.h>
#include <stdint.h>

// Problem constants
#define BATCH 2
#define SEQ   2048
#define DIM   1024
#define HEADS 16
#define DKH   64
#define MTOT  (BATCH * SEQ)   // 4096

// Scratch buffers (device globals — no allocation allowed)
__device__ float g_qp[MTOT * DIM];
__device__ float g_kp[MTOT * DIM];
__device__ float g_vp[MTOT * DIM];
__device__ float g_ao[MTOT * DIM];

// ---------------------------------------------------------------------------
// tf32 round-to-nearest conversion (keeps bits in a float container)
// ---------------------------------------------------------------------------
__device__ __forceinline__ float to_tf32(float x) {
    uint32_t u;
    asm("cvt.rna.tf32.f32 %0, %1;" : "=r"(u) : "f"(x));
    return __uint_as_float(u);
}

#define MMA_TF32(c, a0, a1, a2, a3, b0, b1)                                   \
    asm volatile(                                                             \
        "mma.sync.aligned.m16n8k8.row.col.f32.tf32.tf32.f32 "                 \
        "{%0,%1,%2,%3}, {%4,%5,%6,%7}, {%8,%9}, {%0,%1,%2,%3};"               \
        : "+f"((c)[0]), "+f"((c)[1]), "+f"((c)[2]), "+f"((c)[3])              \
        : "r"(__float_as_uint(a0)), "r"(__float_as_uint(a1)),                 \
          "r"(__float_as_uint(a2)), "r"(__float_as_uint(a3)),                 \
          "r"(__float_as_uint(b0)), "r"(__float_as_uint(b1)))

// ---------------------------------------------------------------------------
// tf32 tensor-core GEMM: C[M,N] = A[M,K] @ W[N,K]^T  (both row-major "NT")
// Block tile 128x128, BK=32, 256 threads = 8 warps (2x4), warp tile 64x32.
// Smem columns permuted within each 16-k block: pos(k) = (k&3)*4 + ((k>>2)&3)
// so each mma fragment pair (two k8 groups) is a single float4 load.
// ---------------------------------------------------------------------------
__global__ __launch_bounds__(256) void sgemm_tf32(const float* __restrict__ A,
                                                  const float* __restrict__ W,
                                                  float* __restrict__ C,
                                                  int M, int N, int K) {
    __shared__ float As[128][36];
    __shared__ float Bs[128][36];

    const int tid  = threadIdx.x;
    const int wid  = tid >> 5;
    const int lane = tid & 31;
    const int bm = blockIdx.y * 128;
    const int bn = blockIdx.x * 128;
    const int wm = (wid >> 2) * 64;   // 0 or 64
    const int wn = (wid & 3) * 32;    // 0,32,64,96
    const int lr = lane >> 2;         // 0..7
    const int lc = lane & 3;          // 0..3

    float acc[4][4][4];
#pragma unroll
    for (int i = 0; i < 4; i++)
#pragma unroll
        for (int j = 0; j < 4; j++)
#pragma unroll
            for (int r = 0; r < 4; r++) acc[i][j][r] = 0.f;

    for (int k0 = 0; k0 < K; k0 += 32) {
        // Prefetch GMEM into registers
        float4 ra[4], rb[4];
#pragma unroll
        for (int it = 0; it < 4; it++) {
            int id  = tid + it * 256;   // 0..1023
            int row = id >> 3;          // 0..127
            int seg = id & 7;           // 0..7
            ra[it] = *(const float4*)(A + (size_t)(bm + row) * K + k0 + seg * 4);
            rb[it] = *(const float4*)(W + (size_t)(bn + row) * K + k0 + seg * 4);
        }

        __syncthreads();   // previous iteration done reading smem

        // Store with tf32 conversion + column permutation
#pragma unroll
        for (int it = 0; it < 4; it++) {
            int id  = tid + it * 256;
            int row = id >> 3;
            int seg = id & 7;
            float va[4] = {ra[it].x, ra[it].y, ra[it].z, ra[it].w};
            float vb[4] = {rb[it].x, rb[it].y, rb[it].z, rb[it].w};
#pragma unroll
            for (int j = 0; j < 4; j++) {
                int k = seg * 4 + j;
                int c = k & 15;
                int col = (k & 16) + (c & 3) * 4 + (c >> 2);
                As[row][col] = to_tf32(va[j]);
                Bs[row][col] = to_tf32(vb[j]);
            }
        }
        __syncthreads();

        // Two 16-k blocks, each = two k8 mma groups
#pragma unroll
        for (int blk = 0; blk < 2; blk++) {
            int kb = blk * 16;
            float4 alo[4], ahi[4], bf[4];
#pragma unroll
            for (int i = 0; i < 4; i++) {
                alo[i] = *(const float4*)&As[wm + i * 16 + lr][kb + lc * 4];
                ahi[i] = *(const float4*)&As[wm + i * 16 + 8 + lr][kb + lc * 4];
            }
#pragma unroll
            for (int j = 0; j < 4; j++)
                bf[j] = *(const float4*)&Bs[wn + j * 8 + lr][kb + lc * 4];
#pragma unroll
            for (int i = 0; i < 4; i++)
#pragma unroll
                for (int j = 0; j < 4; j++) {
                    MMA_TF32(acc[i][j], alo[i].x, ahi[i].x, alo[i].y, ahi[i].y,
                             bf[j].x, bf[j].y);
                    MMA_TF32(acc[i][j], alo[i].z, ahi[i].z, alo[i].w, ahi[i].w,
                             bf[j].z, bf[j].w);
                }
        }
    }

    // Epilogue: c0/c1 at (row, col..col+1), c2/c3 at (row+8, ...)
#pragma unroll
    for (int i = 0; i < 4; i++)
#pragma unroll
        for (int j = 0; j < 4; j++) {
            int row = bm + wm + i * 16 + lr;
            int col = bn + wn + j * 8 + lc * 2;
            *(float2*)&C[(size_t)row * N + col] =
                make_float2(acc[i][j][0], acc[i][j][1]);
            *(float2*)&C[(size_t)(row + 8) * N + col] =
                make_float2(acc[i][j][2], acc[i][j][3]);
        }
}

// ---------------------------------------------------------------------------
// Flash attention, register-tiled, with XOR-swizzled transposed tiles.
// Grid: (SEQ/64, HEADS, BATCH). Block: 256 threads as 16x16.
// Transposed Q^T/K^T use physical float4-column  c ^ (d>>2)  — the transpose
// store becomes ~4-way (was 16-way) conflicted; reads stay conflict-free.
// ---------------------------------------------------------------------------
__global__ __launch_bounds__(256) void attn_kernel(const float* __restrict__ Qp,
                                                   const float* __restrict__ Kp,
                                                   const float* __restrict__ Vp,
                                                   const int* __restrict__ mask,
                                                   float* __restrict__ O) {
    __shared__ float Qt[64 * 64];   // Q^T swizzled, pre-scaled by 1/8
    __shared__ float KP[64 * 64];   // K^T swizzled  /  P natural [row][key]
    __shared__ float Vs[64 * 64];   // V natural [key][dk]

    const int tid = threadIdx.x;
    const int q0 = blockIdx.x * 64;
    const int h  = blockIdx.y;
    const int b  = blockIdx.z;
    const int tx = tid & 15;
    const int ty = tid >> 4;

    const size_t base = (size_t)b * SEQ * DIM + (size_t)h * DKH;

    // Load Q tile transposed + swizzled, scaled by 0.125
#pragma unroll
    for (int it = 0; it < 4; it++) {
        int id = tid + it * 256;
        int r  = id >> 4;          // row 0..63
        int d4 = id & 15;          // d-group: covers d = d4*4..d4*4+3, d>>2 == d4
        float4 v = *(const float4*)(Qp + base + (size_t)(q0 + r) * DIM + d4 * 4);
        int cs = ((r >> 2) ^ d4) * 4 + (r & 3);
        Qt[(d4 * 4 + 0) * 64 + cs] = v.x * 0.125f;
        Qt[(d4 * 4 + 1) * 64 + cs] = v.y * 0.125f;
        Qt[(d4 * 4 + 2) * 64 + cs] = v.z * 0.125f;
        Qt[(d4 * 4 + 3) * 64 + cs] = v.w * 0.125f;
    }

    float acc[4][4];
#pragma unroll
    for (int i = 0; i < 4; i++)
#pragma unroll
        for (int j = 0; j < 4; j++) acc[i][j] = 0.f;
    float m[4], l[4];
#pragma unroll
    for (int i = 0; i < 4; i++) { m[i] = -INFINITY; l[i] = 0.f; }

    const int* mbase = mask + (size_t)b * SEQ * SEQ;

    for (int k0 = 0; k0 < SEQ; k0 += 64) {
        __syncthreads();

        // K^T swizzled into KP; V natural into Vs
#pragma unroll
        for (int it = 0; it < 4; it++) {
            int id = tid + it * 256;
            int r  = id >> 4;
            int d4 = id & 15;
            float4 kv = *(const float4*)(Kp + base + (size_t)(k0 + r) * DIM + d4 * 4);
            int cs = ((r >> 2) ^ d4) * 4 + (r & 3);
            KP[(d4 * 4 + 0) * 64 + cs] = kv.x;
            KP[(d4 * 4 + 1) * 64 + cs] = kv.y;
            KP[(d4 * 4 + 2) * 64 + cs] = kv.z;
            KP[(d4 * 4 + 3) * 64 + cs] = kv.w;
            *(float4*)&Vs[r * 64 + d4 * 4] =
                *(const float4*)(Vp + base + (size_t)(k0 + r) * DIM + d4 * 4);
        }

        int4 mv[4];
#pragma unroll
        for (int i = 0; i < 4; i++)
            mv[i] = *(const int4*)(mbase + (size_t)(q0 + ty * 4 + i) * SEQ + k0 + tx * 4);

        __syncthreads();

        // Scores
        float s[4][4];
#pragma unroll
        for (int i = 0; i < 4; i++)
#pragma unroll
            for (int j = 0; j < 4; j++) s[i][j] = 0.f;

#pragma unroll 8
        for (int d = 0; d < 64; d++) {
            int sw = d >> 2;
            float4 qv = *(const float4*)&Qt[d * 64 + ((ty ^ sw) & 15) * 4];
            float4 kv = *(const float4*)&KP[d * 64 + ((tx ^ sw) & 15) * 4];
            float qa[4] = {qv.x, qv.y, qv.z, qv.w};
            float ka[4] = {kv.x, kv.y, kv.z, kv.w};
#pragma unroll
            for (int i = 0; i < 4; i++)
#pragma unroll
                for (int j = 0; j < 4; j++) s[i][j] += qa[i] * ka[j];
        }

        // Mask (value 1e-9 BEFORE softmax, faithful to reference)
        {
            int mm[4][4];
#pragma unroll
            for (int i = 0; i < 4; i++) {
                mm[i][0] = mv[i].x; mm[i][1] = mv[i].y;
                mm[i][2] = mv[i].z; mm[i][3] = mv[i].w;
            }
#pragma unroll
            for (int i = 0; i < 4; i++)
#pragma unroll
                for (int j = 0; j < 4; j++)
                    s[i][j] = (mm[i][j] == 0) ? 1e-9f : s[i][j];
        }

        // Online softmax stats across the 16 tx lanes
        float mn[4], sc[4], ps[4];
#pragma unroll
        for (int i = 0; i < 4; i++) {
            float tm = fmaxf(fmaxf(s[i][0], s[i][1]), fmaxf(s[i][2], s[i][3]));
#pragma unroll
            for (int w = 1; w < 16; w <<= 1)
                tm = fmaxf(tm, __shfl_xor_sync(0xffffffffu, tm, w));
            mn[i] = fmaxf(m[i], tm);
            sc[i] = __expf(m[i] - mn[i]);
            float p0 = __expf(s[i][0] - mn[i]);
            float p1 = __expf(s[i][1] - mn[i]);
            float p2 = __expf(s[i][2] - mn[i]);
            float p3 = __expf(s[i][3] - mn[i]);
            s[i][0] = p0; s[i][1] = p1; s[i][2] = p2; s[i][3] = p3;
            float sum = p0 + p1 + p2 + p3;
#pragma unroll
            for (int w = 1; w < 16; w <<= 1)
                sum += __shfl_xor_sync(0xffffffffu, sum, w);
            ps[i] = sum;
        }

        __syncthreads();   // done reading K^T before P overwrite

#pragma unroll
        for (int i = 0; i < 4; i++)
            *(float4*)&KP[(ty * 4 + i) * 64 + tx * 4] =
                make_float4(s[i][0], s[i][1], s[i][2], s[i][3]);

#pragma unroll
        for (int i = 0; i < 4; i++) {
            l[i] = l[i] * sc[i] + ps[i];
            m[i] = mn[i];
#pragma unroll
            for (int j = 0; j < 4; j++) acc[i][j] *= sc[i];
        }

        __syncthreads();   // P visible

        // AV
#pragma unroll 4
        for (int kc = 0; kc < 16; kc++) {
            float4 pv[4];
#pragma unroll
            for (int i = 0; i < 4; i++)
                pv[i] = *(const float4*)&KP[(ty * 4 + i) * 64 + kc * 4];
#pragma unroll
            for (int jj = 0; jj < 4; jj++) {
                float4 vv = *(const float4*)&Vs[(kc * 4 + jj) * 64 + tx * 4];
                float pj[4] = { ((const float*)&pv[0])[jj], ((const float*)&pv[1])[jj],
                                ((const float*)&pv[2])[jj], ((const float*)&pv[3])[jj] };
#pragma unroll
                for (int i = 0; i < 4; i++) {
                    acc[i][0] += pj[i] * vv.x;
                    acc[i][1] += pj[i] * vv.y;
                    acc[i][2] += pj[i] * vv.z;
                    acc[i][3] += pj[i] * vv.w;
                }
            }
        }
    }

    // Epilogue
#pragma unroll
    for (int i = 0; i < 4; i++) {
        float inv = 1.f / l[i];
        float* op = O + base + (size_t)(q0 + ty * 4 + i) * DIM + tx * 4;
        *(float4*)op = make_float4(acc[i][0] * inv, acc[i][1] * inv,
                                   acc[i][2] * inv, acc[i][3] * inv);
    }
}

// ---------------------------------------------------------------------------
// Launch
// ---------------------------------------------------------------------------
extern "C" void kernel_launch(void* const* d_in, const int* in_sizes, int n_in,
                              void* d_out, int out_size) {
    const float* Q    = (const float*)d_in[0];
    const float* K    = (const float*)d_in[1];
    const float* V    = (const float*)d_in[2];
    const int*   mask = (const int*)d_in[3];
    const float* Wq   = (const float*)d_in[4];
    const float* Wk   = (const float*)d_in[5];
    const float* Wv   = (const float*)d_in[6];
    const float* Wo   = (const float*)d_in[7];
    float* out = (float*)d_out;

    float *qp, *kp, *vp, *ao;
    cudaGetSymbolAddress((void**)&qp, g_qp);
    cudaGetSymbolAddress((void**)&kp, g_kp);
    cudaGetSymbolAddress((void**)&vp, g_vp);
    cudaGetSymbolAddress((void**)&ao, g_ao);

    dim3 gsz(DIM / 128, MTOT / 128);   // (8, 32)
    sgemm_tf32<<<gsz, 256>>>(Q, Wq, qp, MTOT, DIM, DIM);
    sgemm_tf32<<<gsz, 256>>>(K, Wk, kp, MTOT, DIM, DIM);
    sgemm_tf32<<<gsz, 256>>>(V, Wv, vp, MTOT, DIM, DIM);

    dim3 agrid(SEQ / 64, HEADS, BATCH);   // (32, 16, 2)
    attn_kernel<<<agrid, 256>>>(qp, kp, vp, mask, ao);

    sgemm_tf32<<<gsz, 256>>>(ao, Wo, out, MTOT, DIM, DIM);
}